// round 6
// baseline (speedup 1.0000x reference)
#include <cuda_runtime.h>
#include <math.h>
#include <stdint.h>

#define BB   4
#define CC   32
#define NN   2048
#define PP   12
#define OUTC 32
#define TM   128
#define KT   32
#define ASS  33
#define FSS  33
#define ACCS 264
#define EPSV 1e-5f
#define NEG_SLOPE 0.01f

// smem u32 offsets: double-buffered A[128][33], F[256][33]
#define AB0 0
#define AB1 4224
#define FB0 8448
#define FB1 16896
#define SMEM_BYTES (TM * ACCS * 4)   // 135168 B; stage buffers (101376 B) fit inside

__device__ float g_xp[(size_t)BB * PP * NN * CC];
__device__ float g_ep[(size_t)BB * PP * NN * CC];
__device__ float g_en[(size_t)BB * PP * NN * CC];
__device__ float g_deg[NN];
__device__ float g_delta;

__device__ __forceinline__ uint32_t rna_tf32(float x) {
    uint32_t r;
    asm("cvt.rna.tf32.f32 %0, %1;" : "=r"(r) : "f"(x));
    return r;
}

__device__ __forceinline__ void mma_tf32(float c[4], const uint32_t a[4],
                                         const uint32_t b[2]) {
    asm volatile(
        "mma.sync.aligned.m16n8k8.row.col.f32.tf32.tf32.f32 "
        "{%0,%1,%2,%3}, {%4,%5,%6,%7}, {%8,%9}, {%0,%1,%2,%3};"
        : "+f"(c[0]), "+f"(c[1]), "+f"(c[2]), "+f"(c[3])
        : "r"(a[0]), "r"(a[1]), "r"(a[2]), "r"(a[3]), "r"(b[0]), "r"(b[1]));
}

// ---------------------------------------------------------------------------
__global__ void deg_kernel(const float* __restrict__ A) {
    int row  = blockIdx.x * (blockDim.x >> 5) + (threadIdx.x >> 5);
    int lane = threadIdx.x & 31;
    const float* r = A + (size_t)row * NN;
    float s = 0.f;
    for (int j = lane; j < NN; j += 32) s += r[j];
    #pragma unroll
    for (int o = 16; o; o >>= 1) s += __shfl_xor_sync(0xffffffffu, s, o);
    if (lane == 0) g_deg[row] = s;
}

__global__ void delta_kernel() {
    __shared__ float red[32];
    int tid = threadIdx.x;
    float s = 0.f;
    for (int i = tid; i < NN; i += blockDim.x) s += logf(g_deg[i] + 1.f);
    #pragma unroll
    for (int o = 16; o; o >>= 1) s += __shfl_xor_sync(0xffffffffu, s, o);
    if ((tid & 31) == 0) red[tid >> 5] = s;
    __syncthreads();
    if (tid < 32) {
        float v = (tid < (int)(blockDim.x >> 5)) ? red[tid] : 0.f;
        #pragma unroll
        for (int o = 16; o; o >>= 1) v += __shfl_xor_sync(0xffffffffu, v, o);
        if (tid == 0) g_delta = v / (float)NN;
    }
}

__global__ void transpose_kernel(const float* __restrict__ X) {
    int idx = blockIdx.x * blockDim.x + threadIdx.x;
    if (idx >= BB * PP * NN * CC) return;
    int ch = idx & (CC - 1);
    int j  = (idx >> 5) & (NN - 1);
    int bp = idx >> 16;
    int b = bp / PP, p = bp % PP;
    float x = X[(((size_t)b * CC + ch) * NN + j) * PP + p];
    g_xp[idx] = x;
    g_ep[idx] = expf(x);
    g_en[idx] = expf(-x);
}

// ---------------------------------------------------------------------------
// staging macros (k-interleaved slot: kslot(k) = 8*(k&3) + (k>>2))
// ---------------------------------------------------------------------------
#define LOAD_STAGE(s) do {                                                     \
    const float* _ar = A + (size_t)(i0 + arow) * NN + (size_t)(s) * KT + ah16; \
    pa0 = *(const float4*)(_ar);      pa1 = *(const float4*)(_ar + 4);         \
    pa2 = *(const float4*)(_ar + 8);  pa3 = *(const float4*)(_ar + 12);        \
    size_t _o = (size_t)((s) * KT + 4 * fkq) * CC + fch;                       \
    px0 = xp[_o];          pe0 = epp[_o];          pn0 = enn[_o];              \
    px1 = xp[_o + CC];     pe1 = epp[_o + CC];     pn1 = enn[_o + CC];         \
    px2 = xp[_o + 2*CC];   pe2 = epp[_o + 2*CC];   pn2 = enn[_o + 2*CC];       \
    px3 = xp[_o + 3*CC];   pe3 = epp[_o + 3*CC];   pn3 = enn[_o + 3*CC];       \
} while (0)

#define STA(j, v) _Ab[arow * ASS + 8 * ((j) & 3) + ah4 + ((j) >> 2)] = rna_tf32(v)

#define STF(j, x, e, n2) do {                                                  \
    int _ks = 8 * (j) + fkq;                                                   \
    float _x2 = (x) * (x);                                                     \
    _Fb[fch * FSS + _ks]         = rna_tf32(x);                                \
    _Fb[(32  + fch) * FSS + _ks] = rna_tf32(_x2);                              \
    _Fb[(64  + fch) * FSS + _ks] = rna_tf32(_x2 * (x));                        \
    _Fb[(96  + fch) * FSS + _ks] = rna_tf32(_x2 * _x2);                        \
    _Fb[(128 + fch) * FSS + _ks] = rna_tf32((x) * (e));                        \
    _Fb[(160 + fch) * FSS + _ks] = rna_tf32(e);                                \
    _Fb[(192 + fch) * FSS + _ks] = rna_tf32((x) * (n2));                       \
    _Fb[(224 + fch) * FSS + _ks] = rna_tf32(n2);                               \
} while (0)

#define STORE_STAGE(abuf, fbuf) do {                                           \
    uint32_t* _Ab = smu + (abuf);                                              \
    uint32_t* _Fb = smu + (fbuf);                                              \
    STA(0,  pa0.x); STA(1,  pa0.y); STA(2,  pa0.z); STA(3,  pa0.w);            \
    STA(4,  pa1.x); STA(5,  pa1.y); STA(6,  pa1.z); STA(7,  pa1.w);            \
    STA(8,  pa2.x); STA(9,  pa2.y); STA(10, pa2.z); STA(11, pa2.w);            \
    STA(12, pa3.x); STA(13, pa3.y); STA(14, pa3.z); STA(15, pa3.w);            \
    STF(0, px0, pe0, pn0); STF(1, px1, pe1, pn1);                              \
    STF(2, px2, pe2, pn2); STF(3, px3, pe3, pn3);                              \
} while (0)

#define MMA_STAGE(abuf, fbuf) do {                                             \
    const uint32_t* _As = smu + (abuf);                                        \
    const uint32_t* _Fs = smu + (fbuf);                                        \
    _Pragma("unroll")                                                          \
    for (int kb = 0; kb < 4; kb++) {                                           \
        uint32_t af[4][4];                                                     \
        uint32_t bf[8][2];                                                     \
        _Pragma("unroll")                                                      \
        for (int mt = 0; mt < 4; mt++) {                                       \
            int r0 = (wm * 64 + mt * 16 + lq) * ASS + lr * 8 + 2 * kb;         \
            af[mt][0] = _As[r0];            af[mt][2] = _As[r0 + 1];           \
            af[mt][1] = _As[r0 + 8 * ASS];  af[mt][3] = _As[r0 + 8 * ASS + 1]; \
        }                                                                      \
        _Pragma("unroll")                                                      \
        for (int nt = 0; nt < 8; nt++) {                                       \
            int c0 = (wn * 64 + nt * 8 + lq) * FSS + lr * 8 + 2 * kb;          \
            bf[nt][0] = _Fs[c0];  bf[nt][1] = _Fs[c0 + 1];                     \
        }                                                                      \
        _Pragma("unroll")                                                      \
        for (int mt = 0; mt < 4; mt++)                                         \
            _Pragma("unroll")                                                  \
            for (int nt = 0; nt < 8; nt++)                                     \
                mma_tf32(acc[mt][nt], af[mt], bf[nt]);                         \
    }                                                                          \
} while (0)

// ---------------------------------------------------------------------------
__global__ __launch_bounds__(256, 1)
void pna_kernel(const float* __restrict__ A, const float* __restrict__ Theta,
                const float* __restrict__ Bias, float* __restrict__ out) {
    extern __shared__ float sm[];
    uint32_t* smu = reinterpret_cast<uint32_t*>(sm);

    const int tid  = threadIdx.x;
    const int lane = tid & 31;
    const int wid  = tid >> 5;
    const int bp = blockIdx.y;
    const int i0 = blockIdx.x * TM;
    const int b  = bp / PP, p = bp % PP;
    const float* __restrict__ xp  = g_xp + (size_t)bp * NN * CC;
    const float* __restrict__ epp = g_ep + (size_t)bp * NN * CC;
    const float* __restrict__ enn = g_en + (size_t)bp * NN * CC;

    // MMA ids: 8 warps, warp tile 64x64 (wm 0..1, wn 0..3)
    const int lq = lane >> 2, lr = lane & 3;
    const int wm = wid >> 2, wn = wid & 3;

    // staging ids
    const int arow = tid & 127;          // A row
    const int ah16 = (tid >> 7) * 16;    // k half offset
    const int ah4  = (tid >> 7) * 4;     // slot offset of k-half
    const int fch  = tid & 31;           // F channel
    const int fkq  = tid >> 5;           // F k-quad (k = 4*fkq + j)

    float acc[4][8][4];
    #pragma unroll
    for (int mt = 0; mt < 4; mt++)
        #pragma unroll
        for (int nt = 0; nt < 8; nt++)
            #pragma unroll
            for (int j = 0; j < 4; j++) acc[mt][nt][j] = 0.f;

    float4 pa0, pa1, pa2, pa3;
    float px0, px1, px2, px3, pe0, pe1, pe2, pe3, pn0, pn1, pn2, pn3;

    LOAD_STAGE(0);
    STORE_STAGE(AB0, FB0);
    LOAD_STAGE(1);
    __syncthreads();

    const int NST = NN / KT;
    for (int s = 0; s < NST; s++) {
        const int cab = (s & 1) ? AB1 : AB0;
        const int cfb = (s & 1) ? FB1 : FB0;
        if (s + 1 < NST) STORE_STAGE((s & 1) ? AB0 : AB1, (s & 1) ? FB0 : FB1);
        if (s + 2 < NST) LOAD_STAGE(s + 2);
        MMA_STAGE(cab, cfb);
        __syncthreads();
    }

    // ---- spill accumulators to smem ACC[128][ACCS] ----
    float* ACC = sm;
    #pragma unroll
    for (int mt = 0; mt < 4; mt++) {
        int r = wm * 64 + mt * 16 + lq;
        #pragma unroll
        for (int nt = 0; nt < 8; nt++) {
            int c = wn * 64 + nt * 8 + lr * 2;
            float* a = acc[mt][nt];
            *reinterpret_cast<float2*>(&ACC[r * ACCS + c])       = make_float2(a[0], a[1]);
            *reinterpret_cast<float2*>(&ACC[(r + 8) * ACCS + c]) = make_float2(a[2], a[3]);
        }
    }
    __syncthreads();

    // ---- phase A: aggregator math, in place ----
    for (int e = tid; e < TM * CC; e += 256) {
        int i  = e >> 5;
        int ch = e & 31;
        float* row = &ACC[i * ACCS];
        float S1  = row[ch],       S2  = row[32 + ch];
        float S3  = row[64 + ch],  S4  = row[96 + ch];
        float SXP = row[128 + ch], SEP = row[160 + ch];
        float SXN = row[192 + ch], SEN = row[224 + ch];

        float x    = xp[(size_t)(i0 + i) * CC + ch];
        float dg   = g_deg[i0 + i];
        float dinv = 1.f / fmaxf(dg, EPSV);
        float m1 = S1 * dinv, m2 = S2 * dinv, m3 = S3 * dinv, m4 = S4 * dinv;
        float smax = SXP / (SEP + EPSV);
        float smin = SXN / (SEN + EPSV);
        float var  = fmaxf(m2 - m1 * m1, 0.f);
        float stdv = sqrtf(var + EPSV);
        float x2 = x * x, x3 = x2 * x, x4 = x2 * x2;
        float dist = x2 - 2.f * x * m1 + m2;
        float ed2  = x4 - 4.f * x3 * m1 + 6.f * x2 * m2 - 4.f * x * m3 + m4;
        float dstd = sqrtf(fmaxf(ed2 - dist * dist, 0.f) + EPSV);

        row[ch]        = smin;
        row[32  + ch]  = smax;
        row[64  + ch]  = m1;
        row[96  + ch]  = stdv;
        row[128 + ch]  = var;
        row[160 + ch]  = dist;
        row[192 + ch]  = dstd;
    }
    __syncthreads();

    // ---- phase B: scaler-folded Theta projection (8 warps x 16 rows) ----
    const float delta = g_delta;
    const int o = lane;
    #pragma unroll
    for (int h = 0; h < 2; h++) {
        float s8[8], inv8[8], accO[8];
        #pragma unroll
        for (int r = 0; r < 8; r++) {
            int i = wid * 16 + h * 8 + r;
            float dg = g_deg[i0 + i];
            s8[r]   = logf(dg + 1.f) / delta;
            inv8[r] = 1.f / fmaxf(s8[r], EPSV);
            accO[r] = Bias[o];
        }
        #pragma unroll 4
        for (int f = 0; f < 224; f++) {
            float t0 = Theta[f * OUTC + o];
            float t1 = Theta[(224 + f) * OUTC + o];
            float t2 = Theta[(448 + f) * OUTC + o];
            #pragma unroll
            for (int r = 0; r < 8; r++) {
                float fv = ACC[(wid * 16 + h * 8 + r) * ACCS + f];
                float t  = fmaf(s8[r], t1, fmaf(inv8[r], t2, t0));
                accO[r]  = fmaf(fv, t, accO[r]);
            }
        }
        #pragma unroll
        for (int r = 0; r < 8; r++) {
            int i = wid * 16 + h * 8 + r;
            float v = accO[r];
            v = v > 0.f ? v : NEG_SLOPE * v;
            out[(((size_t)b * OUTC + o) * NN + (i0 + i)) * PP + p] = v;
        }
    }
}

// ---------------------------------------------------------------------------
extern "C" void kernel_launch(void* const* d_in, const int* in_sizes, int n_in,
                              void* d_out, int out_size) {
    const float* X     = (const float*)d_in[0];
    const float* A     = (const float*)d_in[1];
    const float* Theta = (const float*)d_in[2];
    const float* Bias  = (const float*)d_in[3];
    float* out = (float*)d_out;

    cudaFuncSetAttribute(pna_kernel, cudaFuncAttributeMaxDynamicSharedMemorySize,
                         SMEM_BYTES);

    deg_kernel<<<NN / 8, 256>>>(A);
    delta_kernel<<<1, 1024>>>();
    transpose_kernel<<<(BB * PP * NN * CC + 255) / 256, 256>>>(X);

    dim3 grid(NN / TM, BB * PP);
    pna_kernel<<<grid, 256, SMEM_BYTES>>>(A, Theta, Bias, out);
}

// round 8
// speedup vs baseline: 1.1773x; 1.1773x over previous
#include <cuda_runtime.h>
#include <cuda_fp16.h>
#include <math.h>
#include <stdint.h>

#define BB   4
#define CC   32
#define NN   2048
#define PP   12
#define OUTC 32
#define TM   128
#define KT   32
#define EPSV 1e-5f
#define NEG_SLOPE 0.01f

// ---- smem layout (u32 units) ----
#define ASTG   36                    // A stage row stride (32 + 4 pad)
#define FSTG   36                    // F stage row stride
#define A_U32  (128 * ASTG)          // 4608
#define SBSZ   (A_U32 + 256 * FSTG)  // 13824 u32 per stage
#define NBUF   4
#define SMEM_U32 (NBUF * SBSZ)       // 55296 u32 = 221184 B
#define SMEM_BYTES (SMEM_U32 * 4)

// epilogue regions (reuse ring space after mainloop)
#define ACCS     264                 // raw-sum spill stride (floats), 64 rows
#define FEAT_OFF 16896               // feats fp16 [128][116 u32]
#define FBS      116                 // feats/theta row stride in u32 (112 pairs + 4 pad)
#define THB_OFF  31744               // ThetaB fp16 [96][116 u32] -> ends 42880 u32

__device__ float g_atf[(size_t)NN * NN];                 // tf32-rounded A (as float)
__device__ float g_ftf[(size_t)BB * PP * 256 * NN];      // tf32-rounded features [bp][256][j]
__device__ float g_xp[(size_t)BB * PP * NN * CC];
__device__ float g_deg[NN];
__device__ float g_delta;

// ---------------------------------------------------------------------------
__device__ __forceinline__ uint32_t smem_u32(const void* p) {
    uint32_t a;
    asm("{ .reg .u64 t; cvta.to.shared.u64 t, %1; cvt.u32.u64 %0, t; }" : "=r"(a) : "l"(p));
    return a;
}
__device__ __forceinline__ uint32_t rna_tf32(float x) {
    uint32_t r;
    asm("cvt.rna.tf32.f32 %0, %1;" : "=r"(r) : "f"(x));
    return r;
}
__device__ __forceinline__ float tf(float x) { return __uint_as_float(rna_tf32(x)); }

#define CP16(dst, src) \
    asm volatile("cp.async.cg.shared.global [%0], [%1], 16;\n" \
                 :: "r"(dst), "l"(src) : "memory")
#define CP_COMMIT() asm volatile("cp.async.commit_group;\n" ::: "memory")
#define CP_WAIT2()  asm volatile("cp.async.wait_group 2;\n" ::: "memory")

__device__ __forceinline__ void mma_tf32(float c[4], const uint32_t a[4],
                                         const uint32_t b[2]) {
    asm volatile(
        "mma.sync.aligned.m16n8k8.row.col.f32.tf32.tf32.f32 "
        "{%0,%1,%2,%3}, {%4,%5,%6,%7}, {%8,%9}, {%0,%1,%2,%3};"
        : "+f"(c[0]), "+f"(c[1]), "+f"(c[2]), "+f"(c[3])
        : "r"(a[0]), "r"(a[1]), "r"(a[2]), "r"(a[3]), "r"(b[0]), "r"(b[1]));
}
__device__ __forceinline__ void mma_f16(float c[4], const uint32_t a[4],
                                        const uint32_t b[2]) {
    asm volatile(
        "mma.sync.aligned.m16n8k16.row.col.f32.f16.f16.f32 "
        "{%0,%1,%2,%3}, {%4,%5,%6,%7}, {%8,%9}, {%0,%1,%2,%3};"
        : "+f"(c[0]), "+f"(c[1]), "+f"(c[2]), "+f"(c[3])
        : "r"(a[0]), "r"(a[1]), "r"(a[2]), "r"(a[3]), "r"(b[0]), "r"(b[1]));
}
__device__ __forceinline__ uint32_t pack_h2(float lo, float hi) {
    __half2 h = __floats2half2_rn(lo, hi);
    return *reinterpret_cast<uint32_t*>(&h);
}

// ---------------------------------------------------------------------------
__global__ void deg_kernel(const float* __restrict__ A) {
    int row  = blockIdx.x * (blockDim.x >> 5) + (threadIdx.x >> 5);
    int lane = threadIdx.x & 31;
    const float* r = A + (size_t)row * NN;
    float s = 0.f;
    for (int j = lane; j < NN; j += 32) s += r[j];
    #pragma unroll
    for (int o = 16; o; o >>= 1) s += __shfl_xor_sync(0xffffffffu, s, o);
    if (lane == 0) g_deg[row] = s;
}

__global__ void delta_kernel() {
    __shared__ float red[32];
    int tid = threadIdx.x;
    float s = 0.f;
    for (int i = tid; i < NN; i += blockDim.x) s += logf(g_deg[i] + 1.f);
    #pragma unroll
    for (int o = 16; o; o >>= 1) s += __shfl_xor_sync(0xffffffffu, s, o);
    if ((tid & 31) == 0) red[tid >> 5] = s;
    __syncthreads();
    if (tid < 32) {
        float v = (tid < (int)(blockDim.x >> 5)) ? red[tid] : 0.f;
        #pragma unroll
        for (int o = 16; o; o >>= 1) v += __shfl_xor_sync(0xffffffffu, v, o);
        if (tid == 0) g_delta = v / (float)NN;
    }
}

__global__ void transpose_kernel(const float* __restrict__ X) {
    int idx = blockIdx.x * blockDim.x + threadIdx.x;
    if (idx >= BB * PP * NN * CC) return;
    int ch = idx & (CC - 1);
    int j  = (idx >> 5) & (NN - 1);
    int bp = idx >> 16;
    int b = bp / PP, p = bp % PP;
    g_xp[idx] = X[(((size_t)b * CC + ch) * NN + j) * PP + p];
}

__global__ void atf_kernel(const float* __restrict__ A) {
    int idx = blockIdx.x * blockDim.x + threadIdx.x;
    if (idx < NN * NN) g_atf[idx] = tf(A[idx]);
}

// g_ftf[bp][g*32+ch][j] tf32 floats, j contiguous
__global__ void ftf_kernel() {
    __shared__ float sx[64][33];
    int bp = blockIdx.y, j0 = blockIdx.x * 64;
    int t = threadIdx.x;   // 256
    #pragma unroll
    for (int k = 0; k < 8; k++) {
        int idx = t + k * 256;
        sx[idx >> 5][idx & 31] = g_xp[((size_t)bp * NN + j0 + (idx >> 5)) * CC + (idx & 31)];
    }
    __syncthreads();
    int jl = t & 63;
    int cb = t >> 6;   // 0..3
    #pragma unroll
    for (int cq = 0; cq < 8; cq++) {
        int ch = cb + cq * 4;
        float x = sx[jl][ch];
        float x2 = x * x;
        float ep = expf(x), en = expf(-x);
        float* dst = g_ftf + ((size_t)bp * 256 + ch) * NN + j0 + jl;
        const size_t G = (size_t)32 * NN;
        dst[0 * G] = tf(x);
        dst[1 * G] = tf(x2);
        dst[2 * G] = tf(x2 * x);
        dst[3 * G] = tf(x2 * x2);
        dst[4 * G] = tf(x * ep);
        dst[5 * G] = tf(ep);
        dst[6 * G] = tf(x * en);
        dst[7 * G] = tf(en);
    }
}

// ---------------------------------------------------------------------------
__global__ __launch_bounds__(512, 1)
void pna_kernel(const float* __restrict__ Theta, const float* __restrict__ Bias,
                float* __restrict__ out) {
    extern __shared__ uint32_t smu[];
    const uint32_t sbase = smem_u32(smu);

    const int tid = threadIdx.x, lane = tid & 31, wid = tid >> 5;
    const int lq = lane >> 2, lr = lane & 3;
    const int wm = wid >> 2, wn = wid & 3;      // 4x4 warps, 32x64 tiles
    const int bp = blockIdx.y, i0 = blockIdx.x * TM;
    const int b = bp / PP, p = bp % PP;

    // ---- cp.async staging addresses ----
    const float* a_src = g_atf + (size_t)(i0 + (tid >> 2)) * NN + (tid & 3) * 8;
    const float* f_src = g_ftf + ((size_t)bp * 256 + (tid >> 1)) * NN + (tid & 1) * 16;
    const uint32_t a_dst = sbase + ((tid >> 2) * ASTG + (tid & 3) * 8) * 4;
    const uint32_t f_dst = sbase + (A_U32 + (tid >> 1) * FSTG + (tid & 1) * 16) * 4;

    #define ISSUE(s) do {                                                     \
        uint32_t _sb = (uint32_t)(((s) & 3) * (SBSZ * 4));                    \
        const float* _as = a_src + (size_t)(s) * KT;                          \
        const float* _fs = f_src + (size_t)(s) * KT;                          \
        CP16(a_dst + _sb,      _as);                                          \
        CP16(a_dst + _sb + 16, _as + 4);                                      \
        CP16(f_dst + _sb,      _fs);                                          \
        CP16(f_dst + _sb + 16, _fs + 4);                                      \
        CP16(f_dst + _sb + 32, _fs + 8);                                      \
        CP16(f_dst + _sb + 48, _fs + 12);                                     \
        CP_COMMIT();                                                          \
    } while (0)

    float acc[2][8][4];
    #pragma unroll
    for (int mt = 0; mt < 2; mt++)
        #pragma unroll
        for (int nt = 0; nt < 8; nt++)
            #pragma unroll
            for (int j = 0; j < 4; j++) acc[mt][nt][j] = 0.f;

    ISSUE(0);
    ISSUE(1);
    ISSUE(2);

    const int NST = NN / KT;   // 64
    for (int s = 0; s < NST; s++) {
        CP_WAIT2();
        __syncthreads();
        if (s + 3 < NST) ISSUE(s + 3);

        const uint32_t* As_ = smu + (s & 3) * SBSZ;
        const uint32_t* Fs_ = As_ + A_U32;
        #pragma unroll
        for (int kb = 0; kb < 4; kb++) {
            uint32_t af[2][4], bf[8][2];
            #pragma unroll
            for (int mt = 0; mt < 2; mt++) {
                int r = (wm * 32 + mt * 16 + lq) * ASTG + kb * 8 + lr;
                af[mt][0] = As_[r];
                af[mt][1] = As_[r + 8 * ASTG];
                af[mt][2] = As_[r + 4];
                af[mt][3] = As_[r + 8 * ASTG + 4];
            }
            #pragma unroll
            for (int nt = 0; nt < 8; nt++) {
                int c = (wn * 64 + nt * 8 + lq) * FSTG + kb * 8 + lr;
                bf[nt][0] = Fs_[c];
                bf[nt][1] = Fs_[c + 4];
            }
            #pragma unroll
            for (int mt = 0; mt < 2; mt++)
                #pragma unroll
                for (int nt = 0; nt < 8; nt++)
                    mma_tf32(acc[mt][nt], af[mt], bf[nt]);
        }
        __syncthreads();
    }
    #undef ISSUE

    // ---- stage ThetaB [96 n][112 k-pairs] fp16 (ring region now free) ----
    for (int idx = tid; idx < 96 * 112; idx += 512) {
        int p2 = idx / 96, n = idx % 96;
        int q = n >> 5, o = n & 31;
        float f0 = Theta[(size_t)(224 * q + 2 * p2) * OUTC + o];
        float f1 = Theta[(size_t)(224 * q + 2 * p2 + 1) * OUTC + o];
        smu[THB_OFF + n * FBS + p2] = pack_h2(f0, f1);
    }

    // ---- epilogue phase A in two 64-row halves ----
    float* ACCf = reinterpret_cast<float*>(smu);
    __half* Fbh = reinterpret_cast<__half*>(smu + FEAT_OFF);
    const float* xp = g_xp + (size_t)bp * NN * CC;

    #pragma unroll
    for (int h = 0; h < 2; h++) {
        if ((wm >> 1) == h) {
            #pragma unroll
            for (int mt = 0; mt < 2; mt++) {
                int r = (wm & 1) * 32 + mt * 16 + lq;
                #pragma unroll
                for (int nt = 0; nt < 8; nt++) {
                    int c = wn * 64 + nt * 8 + lr * 2;
                    float* a = acc[mt][nt];
                    ACCf[r * ACCS + c]           = a[0];
                    ACCf[r * ACCS + c + 1]       = a[1];
                    ACCf[(r + 8) * ACCS + c]     = a[2];
                    ACCf[(r + 8) * ACCS + c + 1] = a[3];
                }
            }
        }
        __syncthreads();
        for (int e = tid; e < 64 * 32; e += 512) {
            int il = e >> 5, ch = e & 31;
            const float* row = &ACCf[il * ACCS];
            float S1  = row[ch],       S2  = row[32 + ch];
            float S3  = row[64 + ch],  S4  = row[96 + ch];
            float SXP = row[128 + ch], SEP = row[160 + ch];
            float SXN = row[192 + ch], SEN = row[224 + ch];

            int i = i0 + 64 * h + il;
            float x    = xp[(size_t)i * CC + ch];
            float dg   = g_deg[i];
            float dinv = 1.f / fmaxf(dg, EPSV);
            float m1 = S1 * dinv, m2 = S2 * dinv, m3 = S3 * dinv, m4 = S4 * dinv;
            float smax = SXP / (SEP + EPSV);
            float smin = SXN / (SEN + EPSV);
            float var  = fmaxf(m2 - m1 * m1, 0.f);
            float stdv = sqrtf(var + EPSV);
            float x2 = x * x, x3 = x2 * x, x4 = x2 * x2;
            float dist = x2 - 2.f * x * m1 + m2;
            float ed2  = x4 - 4.f * x3 * m1 + 6.f * x2 * m2 - 4.f * x * m3 + m4;
            float dstd = sqrtf(fmaxf(ed2 - dist * dist, 0.f) + EPSV);

            __half* fr = Fbh + (size_t)(64 * h + il) * (2 * FBS);
            fr[0 * 32 + ch] = __float2half(smin);
            fr[1 * 32 + ch] = __float2half(smax);
            fr[2 * 32 + ch] = __float2half(m1);
            fr[3 * 32 + ch] = __float2half(stdv);
            fr[4 * 32 + ch] = __float2half(var);
            fr[5 * 32 + ch] = __float2half(dist);
            fr[6 * 32 + ch] = __float2half(dstd);
        }
        __syncthreads();
    }

    // ---- GEMM2 (fp16): D[128][96] = feats[128x224] @ ThetaB^T ----
    {
        const uint32_t* Fb = smu + FEAT_OFF;
        const uint32_t* Tb = smu + THB_OFF;
        const int wm2 = wid >> 1, wn2 = wid & 1;
        float a2[6][4];
        #pragma unroll
        for (int nt = 0; nt < 6; nt++)
            #pragma unroll
            for (int j = 0; j < 4; j++) a2[nt][j] = 0.f;

        #pragma unroll 2
        for (int kb = 0; kb < 14; kb++) {
            uint32_t af[4], bf[6][2];
            int r = (wm2 * 16 + lq) * FBS + kb * 8 + lr;
            af[0] = Fb[r];
            af[1] = Fb[r + 8 * FBS];
            af[2] = Fb[r + 4];
            af[3] = Fb[r + 8 * FBS + 4];
            #pragma unroll
            for (int nt = 0; nt < 6; nt++) {
                int c = (wn2 * 48 + nt * 8 + lq) * FBS + kb * 8 + lr;
                bf[nt][0] = Tb[c];
                bf[nt][1] = Tb[c + 4];
            }
            #pragma unroll
            for (int nt = 0; nt < 6; nt++)
                mma_f16(a2[nt], af, bf[nt]);
        }
        __syncthreads();
        float* D = reinterpret_cast<float*>(smu);
        int r = wm2 * 16 + lq;
        #pragma unroll
        for (int nt = 0; nt < 6; nt++) {
            int c = wn2 * 48 + nt * 8 + 2 * lr;
            D[r * 100 + c]           = a2[nt][0];
            D[r * 100 + c + 1]       = a2[nt][1];
            D[(r + 8) * 100 + c]     = a2[nt][2];
            D[(r + 8) * 100 + c + 1] = a2[nt][3];
        }
        __syncthreads();

        // ---- combine: out = D0 + s*D1 + inv*D2 + bias, leaky relu ----
        int i = tid >> 2;
        int ob = (tid & 3) * 8;
        float dg = g_deg[i0 + i];
        float sv = logf(dg + 1.f) / g_delta;
        float iv = 1.f / fmaxf(sv, EPSV);
        #pragma unroll
        for (int k = 0; k < 8; k++) {
            int o = ob + k;
            float v = D[i * 100 + o] + sv * D[i * 100 + 32 + o] +
                      iv * D[i * 100 + 64 + o] + Bias[o];
            v = v > 0.f ? v : NEG_SLOPE * v;
            out[(((size_t)b * OUTC + o) * NN + (i0 + i)) * PP + p] = v;
        }
    }
}

// ---------------------------------------------------------------------------
extern "C" void kernel_launch(void* const* d_in, const int* in_sizes, int n_in,
                              void* d_out, int out_size) {
    const float* X     = (const float*)d_in[0];
    const float* A     = (const float*)d_in[1];
    const float* Theta = (const float*)d_in[2];
    const float* Bias  = (const float*)d_in[3];
    float* out = (float*)d_out;

    cudaFuncSetAttribute(pna_kernel, cudaFuncAttributeMaxDynamicSharedMemorySize,
                         SMEM_BYTES);

    deg_kernel<<<NN / 8, 256>>>(A);
    delta_kernel<<<1, 1024>>>();
    transpose_kernel<<<(BB * PP * NN * CC + 255) / 256, 256>>>(X);
    atf_kernel<<<(NN * NN + 1023) / 1024, 1024>>>(A);
    ftf_kernel<<<dim3(NN / 64, BB * PP), 256>>>();

    dim3 grid(NN / TM, BB * PP);
    pna_kernel<<<grid, 512, SMEM_BYTES>>>(Theta, Bias, out);
}

// round 9
// speedup vs baseline: 2.3175x; 1.9685x over previous
#include <cuda_runtime.h>
#include <cuda_fp16.h>
#include <math.h>
#include <stdint.h>

#define BB   4
#define CC   32
#define NN   2048
#define PP   12
#define OUTC 32
#define TM   128
#define KT   64
#define EPSV 1e-5f
#define NEG_SLOPE 0.01f

// ---- smem layout ----
// stage: A[128 rows][72 fp16 (64+8 pad)] = 18432 B ; F[256][72 fp16] = 36864 B
#define A_BYTES   18432
#define SB_BYTES  55296
#define NBUF      4
#define SMEM_BYTES (NBUF * SB_BYTES)      // 221184
// epilogue regions (u32 offsets, reuse ring after mainloop)
#define ACCS     264
#define FEAT_OFF 16896
#define FBS      116
#define THB_OFF  31744

__device__ __half g_ahf[(size_t)NN * NN];               // fp16 A
__device__ __half g_fhf[(size_t)BB * PP * 256 * NN];    // fp16 features [bp][256][j]
__device__ float g_xp[(size_t)BB * PP * NN * CC];
__device__ float g_deg[NN];
__device__ float g_delta;

// ---------------------------------------------------------------------------
__device__ __forceinline__ uint32_t smem_u32(const void* p) {
    uint32_t a;
    asm("{ .reg .u64 t; cvta.to.shared.u64 t, %1; cvt.u32.u64 %0, t; }" : "=r"(a) : "l"(p));
    return a;
}
#define CP16(dst, src) \
    asm volatile("cp.async.cg.shared.global [%0], [%1], 16;\n" \
                 :: "r"(dst), "l"(src) : "memory")
#define CP_COMMIT() asm volatile("cp.async.commit_group;\n" ::: "memory")
#define CP_WAIT2()  asm volatile("cp.async.wait_group 2;\n" ::: "memory")

__device__ __forceinline__ void ldsm_x4(uint32_t r[4], uint32_t addr) {
    asm volatile("ldmatrix.sync.aligned.m8n8.x4.shared.b16 {%0,%1,%2,%3}, [%4];"
        : "=r"(r[0]), "=r"(r[1]), "=r"(r[2]), "=r"(r[3]) : "r"(addr));
}
__device__ __forceinline__ void mma_f16(float c[4], const uint32_t a[4],
                                        const uint32_t b0, const uint32_t b1) {
    asm volatile(
        "mma.sync.aligned.m16n8k16.row.col.f32.f16.f16.f32 "
        "{%0,%1,%2,%3}, {%4,%5,%6,%7}, {%8,%9}, {%0,%1,%2,%3};"
        : "+f"(c[0]), "+f"(c[1]), "+f"(c[2]), "+f"(c[3])
        : "r"(a[0]), "r"(a[1]), "r"(a[2]), "r"(a[3]), "r"(b0), "r"(b1));
}
__device__ __forceinline__ uint32_t pack_h2(float lo, float hi) {
    __half2 h = __floats2half2_rn(lo, hi);
    return *reinterpret_cast<uint32_t*>(&h);
}

// ---------------------------------------------------------------------------
__global__ void deg_kernel(const float* __restrict__ A) {
    int row  = blockIdx.x * (blockDim.x >> 5) + (threadIdx.x >> 5);
    int lane = threadIdx.x & 31;
    const float* r = A + (size_t)row * NN;
    float s = 0.f;
    for (int j = lane; j < NN; j += 32) s += r[j];
    #pragma unroll
    for (int o = 16; o; o >>= 1) s += __shfl_xor_sync(0xffffffffu, s, o);
    if (lane == 0) g_deg[row] = s;
}

__global__ void delta_kernel() {
    __shared__ float red[32];
    int tid = threadIdx.x;
    float s = 0.f;
    for (int i = tid; i < NN; i += blockDim.x) s += logf(g_deg[i] + 1.f);
    #pragma unroll
    for (int o = 16; o; o >>= 1) s += __shfl_xor_sync(0xffffffffu, s, o);
    if ((tid & 31) == 0) red[tid >> 5] = s;
    __syncthreads();
    if (tid < 32) {
        float v = (tid < (int)(blockDim.x >> 5)) ? red[tid] : 0.f;
        #pragma unroll
        for (int o = 16; o; o >>= 1) v += __shfl_xor_sync(0xffffffffu, v, o);
        if (tid == 0) g_delta = v / (float)NN;
    }
}

__global__ void transpose_kernel(const float* __restrict__ X) {
    int idx = blockIdx.x * blockDim.x + threadIdx.x;
    if (idx >= BB * PP * NN * CC) return;
    int ch = idx & (CC - 1);
    int j  = (idx >> 5) & (NN - 1);
    int bp = idx >> 16;
    int b = bp / PP, p = bp % PP;
    g_xp[idx] = X[(((size_t)b * CC + ch) * NN + j) * PP + p];
}

__global__ void ahf_kernel(const float* __restrict__ A) {
    int idx = blockIdx.x * blockDim.x + threadIdx.x;
    if (idx >= NN * NN / 2) return;
    float2 v = reinterpret_cast<const float2*>(A)[idx];
    reinterpret_cast<uint32_t*>(g_ahf)[idx] = pack_h2(v.x, v.y);
}

// g_fhf[bp][g*32+ch][j] fp16, pairs along j
__global__ void fhf_kernel() {
    __shared__ float sx[64][33];
    int bp = blockIdx.y, j0 = blockIdx.x * 64;
    int t = threadIdx.x;   // 256
    #pragma unroll
    for (int k = 0; k < 8; k++) {
        int idx = t + k * 256;
        sx[idx >> 5][idx & 31] = g_xp[((size_t)bp * NN + j0 + (idx >> 5)) * CC + (idx & 31)];
    }
    __syncthreads();
    int jp = t & 31;           // j-pair
    int chb = t >> 5;          // 0..7
    uint32_t* dst = reinterpret_cast<uint32_t*>(g_fhf);
    #pragma unroll
    for (int it = 0; it < 4; it++) {
        int ch = chb * 4 + it;
        float x0 = sx[2 * jp][ch],  x1 = sx[2 * jp + 1][ch];
        float a2 = x0 * x0, b2 = x1 * x1;
        float e0 = expf(x0), e1 = expf(x1);
        float n0 = expf(-x0), n1 = expf(-x1);
        size_t base = (((size_t)bp * 256 + ch) * NN + j0) / 2 + jp;
        const size_t G = (size_t)32 * NN / 2;
        dst[base + 0 * G] = pack_h2(x0, x1);
        dst[base + 1 * G] = pack_h2(a2, b2);
        dst[base + 2 * G] = pack_h2(a2 * x0, b2 * x1);
        dst[base + 3 * G] = pack_h2(a2 * a2, b2 * b2);
        dst[base + 4 * G] = pack_h2(x0 * e0, x1 * e1);
        dst[base + 5 * G] = pack_h2(e0, e1);
        dst[base + 6 * G] = pack_h2(x0 * n0, x1 * n1);
        dst[base + 7 * G] = pack_h2(n0, n1);
    }
}

// ---------------------------------------------------------------------------
__global__ __launch_bounds__(512, 1)
void pna_kernel(const float* __restrict__ Theta, const float* __restrict__ Bias,
                float* __restrict__ out) {
    extern __shared__ uint32_t smu[];
    const uint32_t sbase = smem_u32(smu);

    const int tid = threadIdx.x, lane = tid & 31, wid = tid >> 5;
    const int lq = lane >> 2, lr = lane & 3;
    const int wm = wid >> 2, wn = wid & 3;      // 4x4 warps, warp tile 32x64
    const int bp = blockIdx.y, i0 = blockIdx.x * TM;
    const int b = bp / PP, p = bp % PP;

    // ---- cp.async staging addresses (fp16, 144B row stride) ----
    const __half* a_src = g_ahf + (size_t)(i0 + (tid >> 2)) * NN + (tid & 3) * 16;
    const __half* f_src = g_fhf + ((size_t)bp * 256 + (tid >> 1)) * NN + (tid & 1) * 32;
    const uint32_t a_dst = sbase + (tid >> 2) * 144 + (tid & 3) * 32;
    const uint32_t f_dst = sbase + A_BYTES + (tid >> 1) * 144 + (tid & 1) * 64;

    #define ISSUE(s) do {                                                     \
        uint32_t _sb = (uint32_t)(((s) & 3) * SB_BYTES);                      \
        const __half* _as = a_src + (size_t)(s) * KT;                         \
        const __half* _fs = f_src + (size_t)(s) * KT;                         \
        CP16(a_dst + _sb,      _as);                                          \
        CP16(a_dst + _sb + 16, _as + 8);                                      \
        CP16(f_dst + _sb,      _fs);                                          \
        CP16(f_dst + _sb + 16, _fs + 8);                                      \
        CP16(f_dst + _sb + 32, _fs + 16);                                     \
        CP16(f_dst + _sb + 48, _fs + 24);                                     \
        CP_COMMIT();                                                          \
    } while (0)

    // ldmatrix per-lane base addresses
    const uint32_t a_lm = sbase +
        (wm * 32 + (lane & 7) + ((lane >> 3) & 1) * 8) * 144 + ((lane >> 4) & 1) * 16;
    const uint32_t b_lm = sbase + A_BYTES +
        (wn * 64 + (lane & 7) + ((lane >> 4) & 1) * 8) * 144 + ((lane >> 3) & 1) * 16;

    float acc[2][8][4];
    #pragma unroll
    for (int mt = 0; mt < 2; mt++)
        #pragma unroll
        for (int nt = 0; nt < 8; nt++)
            #pragma unroll
            for (int j = 0; j < 4; j++) acc[mt][nt][j] = 0.f;

    ISSUE(0);
    ISSUE(1);
    ISSUE(2);

    const int NST = NN / KT;   // 32
    for (int s = 0; s < NST; s++) {
        CP_WAIT2();
        __syncthreads();
        if (s + 3 < NST) ISSUE(s + 3); else CP_COMMIT();   // keep group invariant

        const uint32_t stg = (uint32_t)((s & 3) * SB_BYTES);
        #pragma unroll
        for (int kb = 0; kb < 4; kb++) {
            uint32_t af[2][4], bf[4][4];
            #pragma unroll
            for (int mt = 0; mt < 2; mt++)
                ldsm_x4(af[mt], a_lm + stg + mt * 2304 + kb * 32);
            #pragma unroll
            for (int ntp = 0; ntp < 4; ntp++)
                ldsm_x4(bf[ntp], b_lm + stg + ntp * 2304 + kb * 32);
            #pragma unroll
            for (int mt = 0; mt < 2; mt++)
                #pragma unroll
                for (int nt = 0; nt < 8; nt++)
                    mma_f16(acc[mt][nt], af[mt], bf[nt >> 1][(nt & 1) * 2],
                            bf[nt >> 1][(nt & 1) * 2 + 1]);
        }
        __syncthreads();
    }
    #undef ISSUE

    // ---- stage ThetaB [96 n][112 k-pairs] fp16 (ring region now free) ----
    for (int idx = tid; idx < 96 * 112; idx += 512) {
        int p2 = idx / 96, n = idx % 96;
        int q = n >> 5, o = n & 31;
        float f0 = Theta[(size_t)(224 * q + 2 * p2) * OUTC + o];
        float f1 = Theta[(size_t)(224 * q + 2 * p2 + 1) * OUTC + o];
        smu[THB_OFF + n * FBS + p2] = pack_h2(f0, f1);
    }

    // ---- epilogue phase A in two 64-row halves ----
    float* ACCf = reinterpret_cast<float*>(smu);
    __half* Fbh = reinterpret_cast<__half*>(smu + FEAT_OFF);
    const float* xp = g_xp + (size_t)bp * NN * CC;

    #pragma unroll
    for (int h = 0; h < 2; h++) {
        if ((wm >> 1) == h) {
            #pragma unroll
            for (int mt = 0; mt < 2; mt++) {
                int r = (wm & 1) * 32 + mt * 16 + lq;
                #pragma unroll
                for (int nt = 0; nt < 8; nt++) {
                    int c = wn * 64 + nt * 8 + lr * 2;
                    float* a = acc[mt][nt];
                    ACCf[r * ACCS + c]           = a[0];
                    ACCf[r * ACCS + c + 1]       = a[1];
                    ACCf[(r + 8) * ACCS + c]     = a[2];
                    ACCf[(r + 8) * ACCS + c + 1] = a[3];
                }
            }
        }
        __syncthreads();
        for (int e = tid; e < 64 * 32; e += 512) {
            int il = e >> 5, ch = e & 31;
            const float* row = &ACCf[il * ACCS];
            float S1  = row[ch],       S2  = row[32 + ch];
            float S3  = row[64 + ch],  S4  = row[96 + ch];
            float SXP = row[128 + ch], SEP = row[160 + ch];
            float SXN = row[192 + ch], SEN = row[224 + ch];

            int i = i0 + 64 * h + il;
            float x    = xp[(size_t)i * CC + ch];
            float dg   = g_deg[i];
            float dinv = 1.f / fmaxf(dg, EPSV);
            float m1 = S1 * dinv, m2 = S2 * dinv, m3 = S3 * dinv, m4 = S4 * dinv;
            float smax = SXP / (SEP + EPSV);
            float smin = SXN / (SEN + EPSV);
            float var  = fmaxf(m2 - m1 * m1, 0.f);
            float stdv = sqrtf(var + EPSV);
            float x2 = x * x, x3 = x2 * x, x4 = x2 * x2;
            float dist = x2 - 2.f * x * m1 + m2;
            float ed2  = x4 - 4.f * x3 * m1 + 6.f * x2 * m2 - 4.f * x * m3 + m4;
            float dstd = sqrtf(fmaxf(ed2 - dist * dist, 0.f) + EPSV);

            __half* fr = Fbh + (size_t)(64 * h + il) * (2 * FBS);
            fr[0 * 32 + ch] = __float2half(smin);
            fr[1 * 32 + ch] = __float2half(smax);
            fr[2 * 32 + ch] = __float2half(m1);
            fr[3 * 32 + ch] = __float2half(stdv);
            fr[4 * 32 + ch] = __float2half(var);
            fr[5 * 32 + ch] = __float2half(dist);
            fr[6 * 32 + ch] = __float2half(dstd);
        }
        __syncthreads();
    }

    // ---- GEMM2 (fp16): D[128][96] = feats[128x224] @ ThetaB^T ----
    {
        const uint32_t* Fb = smu + FEAT_OFF;
        const uint32_t* Tb = smu + THB_OFF;
        const int wm2 = wid >> 1, wn2 = wid & 1;
        float a2[6][4];
        #pragma unroll
        for (int nt = 0; nt < 6; nt++)
            #pragma unroll
            for (int j = 0; j < 4; j++) a2[nt][j] = 0.f;

        #pragma unroll 2
        for (int kb = 0; kb < 14; kb++) {
            uint32_t af[4], bfv[6][2];
            int r = (wm2 * 16 + lq) * FBS + kb * 8 + lr;
            af[0] = Fb[r];
            af[1] = Fb[r + 8 * FBS];
            af[2] = Fb[r + 4];
            af[3] = Fb[r + 8 * FBS + 4];
            #pragma unroll
            for (int nt = 0; nt < 6; nt++) {
                int c = (wn2 * 48 + nt * 8 + lq) * FBS + kb * 8 + lr;
                bfv[nt][0] = Tb[c];
                bfv[nt][1] = Tb[c + 4];
            }
            #pragma unroll
            for (int nt = 0; nt < 6; nt++)
                mma_f16(a2[nt], af, bfv[nt][0], bfv[nt][1]);
        }
        __syncthreads();
        float* D = reinterpret_cast<float*>(smu);
        int r = wm2 * 16 + lq;
        #pragma unroll
        for (int nt = 0; nt < 6; nt++) {
            int c = wn2 * 48 + nt * 8 + 2 * lr;
            D[r * 100 + c]           = a2[nt][0];
            D[r * 100 + c + 1]       = a2[nt][1];
            D[(r + 8) * 100 + c]     = a2[nt][2];
            D[(r + 8) * 100 + c + 1] = a2[nt][3];
        }
        __syncthreads();

        int i = tid >> 2;
        int ob = (tid & 3) * 8;
        float dg = g_deg[i0 + i];
        float sv = logf(dg + 1.f) / g_delta;
        float iv = 1.f / fmaxf(sv, EPSV);
        #pragma unroll
        for (int k = 0; k < 8; k++) {
            int o = ob + k;
            float v = D[i * 100 + o] + sv * D[i * 100 + 32 + o] +
                      iv * D[i * 100 + 64 + o] + Bias[o];
            v = v > 0.f ? v : NEG_SLOPE * v;
            out[(((size_t)b * OUTC + o) * NN + (i0 + i)) * PP + p] = v;
        }
    }
}

// ---------------------------------------------------------------------------
extern "C" void kernel_launch(void* const* d_in, const int* in_sizes, int n_in,
                              void* d_out, int out_size) {
    const float* X     = (const float*)d_in[0];
    const float* A     = (const float*)d_in[1];
    const float* Theta = (const float*)d_in[2];
    const float* Bias  = (const float*)d_in[3];
    float* out = (float*)d_out;

    cudaFuncSetAttribute(pna_kernel, cudaFuncAttributeMaxDynamicSharedMemorySize,
                         SMEM_BYTES);

    deg_kernel<<<NN / 8, 256>>>(A);
    delta_kernel<<<1, 1024>>>();
    transpose_kernel<<<(BB * PP * NN * CC + 255) / 256, 256>>>(X);
    ahf_kernel<<<(NN * NN / 2 + 1023) / 1024, 1024>>>(A);
    fhf_kernel<<<dim3(NN / 64, BB * PP), 256>>>();

    dim3 grid(NN / TM, BB * PP);
    pna_kernel<<<grid, 512, SMEM_BYTES>>>(Theta, Bias, out);
}